// round 15
// baseline (speedup 1.0000x reference)
#include <cuda_runtime.h>
#include <cuda_bf16.h>
#include <math.h>
#include <stdint.h>

// Problem shapes (fixed)
#define BDIM 32
#define SDIM 2048
#define HDIM 512
#define EDIM 512
#define ROWS (BDIM * SDIM)   // 65536
#define MTILES (ROWS / 128)  // 512 m-tiles; 16 per batch
#define NBX 4                // n-blocks of 128

// Scratch (device globals: allocation-free rule)
__device__ float g_w[ROWS];
__device__ float g_denInv[ROWS];
__device__ float g_tsum[(size_t)MTILES * EDIM];   // per (m-tile, col) 128-row sums
__device__ unsigned g_flag[MTILES * NBX];         // publish flags per (m-tile, n-block)
__device__ float g_bil[(size_t)EDIM * HDIM];      // 1 MB: tf32-rounded, k-interleaved Wb

// ======================= helpers =======================
__device__ __forceinline__ uint32_t smem_u32(const void* p) {
    uint32_t a;
    asm("{ .reg .u64 t; cvta.to.shared.u64 t, %1; cvt.u32.u64 %0, t; }" : "=r"(a) : "l"(p));
    return a;
}
__device__ __forceinline__ void cp16(void* sdst, const void* gsrc) {
    uint32_t d = smem_u32(sdst);
    asm volatile("cp.async.cg.shared.global [%0], [%1], 16;" :: "r"(d), "l"(gsrc) : "memory");
}
#define CP_COMMIT() asm volatile("cp.async.commit_group;" ::: "memory")
#define CP_WAIT(n)  asm volatile("cp.async.wait_group %0;" :: "n"(n) : "memory")

__device__ __forceinline__ uint32_t f2tf32(float f) {
    uint32_t o;
    asm("cvt.rna.tf32.f32 %0, %1;" : "=r"(o) : "f"(f));
    return o;
}
__device__ __forceinline__ float f2tf32f(float f) { return __uint_as_float(f2tf32(f)); }
__device__ __forceinline__ float tanh_fast(float x) {
    float y;
    asm("tanh.approx.f32 %0, %1;" : "=f"(y) : "f"(x));
    return y;
}
__device__ __forceinline__ void mma_tf32(float* c, const uint32_t* a, const uint32_t* b) {
    asm volatile(
        "mma.sync.aligned.m16n8k8.row.col.f32.tf32.tf32.f32 "
        "{%0,%1,%2,%3}, {%4,%5,%6,%7}, {%8,%9}, {%0,%1,%2,%3};"
        : "+f"(c[0]), "+f"(c[1]), "+f"(c[2]), "+f"(c[3])
        : "r"(a[0]), "r"(a[1]), "r"(a[2]), "r"(a[3]), "r"(b[0]), "r"(b[1]));
}

// ======================= Kernel 0: reset look-back flags =======================
__global__ void RA_reset_kernel() {
    g_flag[blockIdx.x * 256 + threadIdx.x] = 0u;
}

// ======================= Kernel 0b: tf32-round + k-interleave Wb (1 MB) =======================
// Within each 8-k group: out = {k0,k4,k1,k5, k2,k6,k3,k7}
__global__ void RA_interleave_kernel(const float* __restrict__ src, float* __restrict__ dst,
                                     int ngroups) {
    int idx = blockIdx.x * 256 + threadIdx.x;
    if (idx >= ngroups) return;
    const float4* s = (const float4*)src + (size_t)idx * 2;
    float4 v0 = s[0], v1 = s[1];
    float4 o0 = make_float4(f2tf32f(v0.x), f2tf32f(v1.x), f2tf32f(v0.y), f2tf32f(v1.y));
    float4 o1 = make_float4(f2tf32f(v0.z), f2tf32f(v1.z), f2tf32f(v0.w), f2tf32f(v1.w));
    float4* d = (float4*)dst + (size_t)idx * 2;
    d[0] = o0;
    d[1] = o1;
}

// ======================= Kernel 1: w = exp(alpha . Wa + ba) =======================
__global__ void RA_w_kernel(const float* __restrict__ alpha, const float* __restrict__ Wa,
                            const float* __restrict__ ba) {
    __shared__ __align__(16) float sWa[HDIM];
    int tid = threadIdx.x;
    for (int i = tid; i < HDIM; i += blockDim.x) sWa[i] = Wa[i];
    __syncthreads();
    int wid = tid >> 5, lane = tid & 31;
    int row = blockIdx.x * 8 + wid;
    const float4* a4 = (const float4*)(alpha + (size_t)row * HDIM);
    const float4* w4 = (const float4*)sWa;
    float sum = 0.f;
#pragma unroll
    for (int i = 0; i < 4; i++) {
        float4 a = a4[lane + i * 32];
        float4 w = w4[lane + i * 32];
        sum += a.x * w.x + a.y * w.y + a.z * w.z + a.w * w.w;
    }
#pragma unroll
    for (int o = 16; o > 0; o >>= 1) sum += __shfl_xor_sync(0xffffffffu, sum, o);
    if (lane == 0) g_w[row] = expf(sum + ba[0]);
}

// ======================= Kernel 2: denInv = 1/(cumsum(w)+1e-10), per b =======================
__global__ void RA_den_kernel() {
    __shared__ float sw[SDIM];
    __shared__ float sx[32];
    int b = blockIdx.x, tid = threadIdx.x;
    for (int i = tid; i < SDIM; i += 256) sw[i] = g_w[b * SDIM + i];
    __syncthreads();
    if (tid < 32) {
        int lane = tid;
        int base = lane * 64;
        float s = 0.f;
        for (int i = 0; i < 64; i++) { s += sw[base + i]; sw[base + i] = s; }
        float tot = s;
#pragma unroll
        for (int o = 1; o < 32; o <<= 1) {
            float t = __shfl_up_sync(0xffffffffu, tot, o);
            if (lane >= o) tot += t;
        }
        sx[lane] = tot - s;
    }
    __syncthreads();
    float* di = g_denInv + b * SDIM;
    for (int i = tid; i < SDIM; i += 256)
        di[i] = 1.0f / (sw[i] + sx[i >> 6] + 1e-10f);
}

// ======================= Kernel 3: fused GEMM + epilogue + single-pass scan =======================
// 128x128 CTA tile, 256 threads, 8 warps of 32(M)x64(N), NSTAGE=3 (CP_WAIT(1):
// each load hidden under TWO k-tiles of compute), 2 CTAs/SM.
#define MT 128
#define NT 128
#define KB 32
#define KT (HDIM / KB)   // 16 k-tiles
#define NSTAGE 3
#define LDA 36           // KB + 4 pad floats
#define A_ST_FL (MT * LDA)           // 4608
#define B_ST_FL (NT * LDA)           // 4608
#define ST_FL (A_ST_FL + B_ST_FL)    // 9216
#define GEMM_SMEM_FL (NSTAGE * ST_FL + NT + 4 * NT + NT)  // + bb + sCh[4] + sPre
#define GEMM_SMEM (GEMM_SMEM_FL * 4)                      // 113664 B -> 2 CTAs/SM (227.3KB)

__device__ __forceinline__ void gemm_load_stage(float* smem, int s, int kt,
                                                const float* __restrict__ A,
                                                int m0, int n0, int tid) {
    float* sA = smem + s * ST_FL;
    float* sB = sA + A_ST_FL;
    // A: 128x32 floats = 1024 float4; 256 thr -> 4 each (direct from beta, fp32)
#pragma unroll
    for (int i = 0; i < 4; i++) {
        int id = tid + i * 256;
        int r = id >> 3, c4 = id & 7;
        cp16(sA + r * LDA + c4 * 4, A + (size_t)(m0 + r) * HDIM + kt * KB + c4 * 4);
    }
    // B: 128x32 from interleaved tf32 Wb
#pragma unroll
    for (int i = 0; i < 4; i++) {
        int id = tid + i * 256;
        int r = id >> 3, c4 = id & 7;
        cp16(sB + r * LDA + c4 * 4, g_bil + (size_t)(n0 + r) * HDIM + kt * KB + c4 * 4);
    }
}

__global__ void __launch_bounds__(256, 2) RA_gemm_kernel(
    const float* __restrict__ Abeta,   // [ROWS, HDIM]
    const float* __restrict__ bb,      // [EDIM]
    const float* __restrict__ embed,   // [ROWS, EDIM]
    float* __restrict__ out)           // [ROWS, EDIM]
{
    extern __shared__ float smem[];
    int tid = threadIdx.x, wid = tid >> 5, lane = tid & 31;
    int g = lane >> 2, tg = lane & 3;
    int bx = blockIdx.x, by = blockIdx.y;
    int n0 = bx * NT, m0 = by * MT;
    int wm = wid & 3, wn = wid >> 2;   // 4 x 2 warp grid; warp tile 32(M) x 64(N)
    int t_local = by & 15;
    int mtile_base = by - t_local;

    float* sBB  = smem + NSTAGE * ST_FL;
    float* sCh  = sBB + NT;            // [4][NT]
    float* sPre = sCh + 4 * NT;
    if (tid < NT) sBB[tid] = bb[n0 + tid];

    // prologue: stages 0 and 1 in flight
    gemm_load_stage(smem, 0, 0, Abeta, m0, n0, tid);
    CP_COMMIT();
    gemm_load_stage(smem, 1, 1, Abeta, m0, n0, tid);
    CP_COMMIT();

    float acc[2][8][4];
#pragma unroll
    for (int i = 0; i < 2; i++)
#pragma unroll
        for (int j = 0; j < 8; j++)
#pragma unroll
            for (int q = 0; q < 4; q++) acc[i][j][q] = 0.f;

    for (int kt = 0; kt < KT; kt++) {
        CP_WAIT(1);              // stage kt complete (kt+1 may still be in flight)
        __syncthreads();
        if (kt + 2 < KT)
            gemm_load_stage(smem, (kt + 2) % NSTAGE, kt + 2, Abeta, m0, n0, tid);
        CP_COMMIT();             // always commit (possibly-empty group keeps ledger aligned)

        int buf = kt % NSTAGE;
        const float* sA = smem + buf * ST_FL + (wm * 32 + g) * LDA + tg;
        const float* sB = smem + buf * ST_FL + A_ST_FL + (wn * 64 + g) * LDA + 2 * tg;
#pragma unroll
        for (int k8 = 0; k8 < KB / 8; k8++) {
            const float* pA = sA + k8 * 8;
            const float* pB = sB + k8 * 8;
            uint32_t a[2][4];
#pragma unroll
            for (int i = 0; i < 2; i++) {
                a[i][0] = f2tf32(pA[(i * 16 + 0) * LDA + 0]);
                a[i][1] = f2tf32(pA[(i * 16 + 8) * LDA + 0]);
                a[i][2] = f2tf32(pA[(i * 16 + 0) * LDA + 4]);
                a[i][3] = f2tf32(pA[(i * 16 + 8) * LDA + 4]);
            }
#pragma unroll
            for (int j = 0; j < 8; j++) {
                float2 bf = *(const float2*)(pB + (j * 8) * LDA);  // interleaved: k=tg,k=tg+4
                uint32_t b[2];
                b[0] = __float_as_uint(bf.x);
                b[1] = __float_as_uint(bf.y);
#pragma unroll
                for (int i = 0; i < 2; i++) mma_tf32(acc[i][j], a[i], b);
            }
        }
    }

    // ---- step 1: transform acc -> g values; per-column sums over this warp's 32 rows ----
    int m_base = m0 + wm * 32, n_base = n0 + wn * 64;
    float cs[8][2];
#pragma unroll
    for (int j = 0; j < 8; j++) { cs[j][0] = 0.f; cs[j][1] = 0.f; }

#pragma unroll
    for (int i = 0; i < 2; i++) {
#pragma unroll
        for (int r2 = 0; r2 < 2; r2++) {
            int row = m_base + i * 16 + r2 * 8 + g;
            float wr = g_w[row];
            const float* erow = embed + (size_t)row * EDIM;
#pragma unroll
            for (int j = 0; j < 8; j++) {
                int nc = n_base + j * 8 + tg * 2;
                float2 ee = *(const float2*)(erow + nc);
                float b0 = sBB[nc - n0], b1 = sBB[nc - n0 + 1];
                float vx = wr * tanh_fast(acc[i][j][r2 * 2 + 0] + b0) * ee.x;
                float vy = wr * tanh_fast(acc[i][j][r2 * 2 + 1] + b1) * ee.y;
                acc[i][j][r2 * 2 + 0] = vx;
                acc[i][j][r2 * 2 + 1] = vy;
                cs[j][0] += vx;
                cs[j][1] += vy;
            }
        }
    }
#pragma unroll
    for (int j = 0; j < 8; j++) {
#pragma unroll
        for (int q = 0; q < 2; q++) {
            float v = cs[j][q];
            v += __shfl_xor_sync(0xffffffffu, v, 4);
            v += __shfl_xor_sync(0xffffffffu, v, 8);
            v += __shfl_xor_sync(0xffffffffu, v, 16);
            cs[j][q] = v;
        }
    }
    // ---- step 2: stash 32-row block sums ----
    if (g == 0) {
        float* dst = sCh + wm * NT;
#pragma unroll
        for (int j = 0; j < 8; j++) {
            int c = wn * 64 + j * 8 + tg * 2;
            dst[c] = cs[j][0];
            dst[c + 1] = cs[j][1];
        }
    }
    __syncthreads();

    // ---- step 3: publish 128-row tile sum + release flag ----
    if (tid < NT) {
        float ts = sCh[tid] + sCh[NT + tid] + sCh[2 * NT + tid] + sCh[3 * NT + tid];
        g_tsum[(size_t)by * EDIM + n0 + tid] = ts;
    }
    __threadfence();
    __syncthreads();
    if (tid == 0)
        asm volatile("st.release.gpu.b32 [%0], %1;"
                     :: "l"(&g_flag[by * NBX + bx]), "r"(1u) : "memory");

    // ---- step 4: look-back ----
    if (tid < t_local) {
        const unsigned* f = &g_flag[(mtile_base + tid) * NBX + bx];
        unsigned v;
        unsigned ns = 64;
        for (;;) {
            asm volatile("ld.acquire.gpu.b32 %0, [%1];" : "=r"(v) : "l"(f) : "memory");
            if (v) break;
            __nanosleep(ns);
            if (ns < 1024) ns <<= 1;
        }
    }
    __syncthreads();
    if (tid < NT) {
        float p = 0.f;
        for (int q = 0; q < t_local; q++)
            p += g_tsum[(size_t)(mtile_base + q) * EDIM + n0 + tid];
        sPre[tid] = p;
    }
    __syncthreads();

    // ---- step 5: interleaved in-warp prefix + divide + store ----
    float dinv[4];
#pragma unroll
    for (int q = 0; q < 4; q++) dinv[q] = g_denInv[m_base + q * 8 + g];

#pragma unroll
    for (int j = 0; j < 8; j++) {
        int c = wn * 64 + j * 8 + tg * 2;
        float carryx = sPre[c], carryy = sPre[c + 1];
#pragma unroll
        for (int bblk = 0; bblk < 3; bblk++) {
            if (bblk < wm) {
                carryx += sCh[bblk * NT + c];
                carryy += sCh[bblk * NT + c + 1];
            }
        }
#pragma unroll
        for (int q = 0; q < 4; q++) {
            int i = q >> 1, r2 = q & 1;
            float sxv = acc[i][j][r2 * 2 + 0];
            float syv = acc[i][j][r2 * 2 + 1];
#pragma unroll
            for (int o = 4; o <= 16; o <<= 1) {
                float ux = __shfl_up_sync(0xffffffffu, sxv, o);
                float uy = __shfl_up_sync(0xffffffffu, syv, o);
                if (lane >= o) { sxv += ux; syv += uy; }
            }
            float totx = __shfl_sync(0xffffffffu, sxv, 28 + tg);
            float toty = __shfl_sync(0xffffffffu, syv, 28 + tg);
            int row = m_base + q * 8 + g;
            float d = dinv[q];
            float2 r;
            r.x = (carryx + sxv) * d;
            r.y = (carryy + syv) * d;
            *(float2*)(out + (size_t)row * EDIM + n_base + j * 8 + tg * 2) = r;
            carryx += totx;
            carryy += toty;
        }
    }
}

// ======================= Host launch =======================
extern "C" void kernel_launch(void* const* d_in, const int* in_sizes, int n_in,
                              void* d_out, int out_size) {
    const float* alpha   = (const float*)d_in[0];
    const float* beta_in = (const float*)d_in[1];
    const float* embed   = (const float*)d_in[2];
    const float* Wb      = (const float*)d_in[3];
    const float* bb      = (const float*)d_in[4];
    const float* Wa      = (const float*)d_in[5];
    const float* ba      = (const float*)d_in[6];
    float* out = (float*)d_out;

    float* d_bil; cudaGetSymbolAddress((void**)&d_bil, g_bil);

    RA_reset_kernel<<<MTILES * NBX / 256, 256>>>();
    RA_w_kernel<<<ROWS / 8, 256>>>(alpha, Wa, ba);
    RA_den_kernel<<<BDIM, 256>>>();
    RA_interleave_kernel<<<(EDIM * (HDIM / 8)) / 256, 256>>>(Wb, d_bil, EDIM * (HDIM / 8));
    cudaFuncSetAttribute(RA_gemm_kernel, cudaFuncAttributeMaxDynamicSharedMemorySize, GEMM_SMEM);
    RA_gemm_kernel<<<dim3(NBX, ROWS / MT), 256, GEMM_SMEM>>>(beta_in, bb, embed, out);
    (void)in_sizes; (void)n_in; (void)out_size;
}

// round 17
// speedup vs baseline: 1.2728x; 1.2728x over previous
#include <cuda_runtime.h>
#include <cuda_fp16.h>
#include <math.h>
#include <stdint.h>

// Problem shapes (fixed)
#define BDIM 32
#define SDIM 2048
#define HDIM 512
#define EDIM 512
#define ROWS (BDIM * SDIM)   // 65536
#define MTILES (ROWS / 128)  // 512 m-tiles; 16 per batch
#define NBX 4                // n-blocks of 128

// Scratch (device globals: allocation-free rule)
__device__ float g_w[ROWS];
__device__ float g_denInv[ROWS];
__device__ float g_tsum[(size_t)MTILES * EDIM];   // per (m-tile, col) 128-row sums
__device__ unsigned g_flag[MTILES * NBX];         // publish flags per (m-tile, n-block)
__device__ __half g_ahl[(size_t)ROWS * HDIM];     // 64 MB: fp16 k-interleaved beta
__device__ __half g_bhl[(size_t)EDIM * HDIM];     // 0.5 MB: fp16 k-interleaved Wb

// ======================= helpers =======================
__device__ __forceinline__ uint32_t smem_u32(const void* p) {
    uint32_t a;
    asm("{ .reg .u64 t; cvta.to.shared.u64 t, %1; cvt.u32.u64 %0, t; }" : "=r"(a) : "l"(p));
    return a;
}
__device__ __forceinline__ void cp16(void* sdst, const void* gsrc) {
    uint32_t d = smem_u32(sdst);
    asm volatile("cp.async.cg.shared.global [%0], [%1], 16;" :: "r"(d), "l"(gsrc) : "memory");
}
#define CP_COMMIT() asm volatile("cp.async.commit_group;" ::: "memory")
#define CP_WAIT(n)  asm volatile("cp.async.wait_group %0;" :: "n"(n) : "memory")

__device__ __forceinline__ float tanh_fast(float x) {
    float y;
    asm("tanh.approx.f32 %0, %1;" : "=f"(y) : "f"(x));
    return y;
}
// fp16 m16n8k16, fp32 accumulate. C-fragment layout == tf32 m16n8k8 (validated).
__device__ __forceinline__ void mma_f16(float* c, const uint32_t* a, uint32_t b0, uint32_t b1) {
    asm volatile(
        "mma.sync.aligned.m16n8k16.row.col.f32.f16.f16.f32 "
        "{%0,%1,%2,%3}, {%4,%5,%6,%7}, {%8,%9}, {%0,%1,%2,%3};"
        : "+f"(c[0]), "+f"(c[1]), "+f"(c[2]), "+f"(c[3])
        : "r"(a[0]), "r"(a[1]), "r"(a[2]), "r"(a[3]), "r"(b0), "r"(b1));
}

// ======================= Kernel 0: reset look-back flags =======================
__global__ void RA_reset_kernel() {
    g_flag[blockIdx.x * 256 + threadIdx.x] = 0u;
}

// ======================= Kernel 0b: fp32 -> fp16 with k-interleave =======================
// Per 16-k group, output order {k0,k1,k8,k9, k2,k3,k10,k11, k4,k5,k12,k13, k6,k7,k14,k15}
// so an 8-byte load at half-offset 4*tg yields {2tg,2tg+1,2tg+8,2tg+9} = (a0,a2) / (b0,b1).
__global__ void RA_tohalf_kernel(const float* __restrict__ src, __half* __restrict__ dst,
                                 int ngroups) {
    int idx = blockIdx.x * 256 + threadIdx.x;
    if (idx >= ngroups) return;
    const float4* s = (const float4*)src + (size_t)idx * 4;
    float4 v0 = s[0], v1 = s[1], v2 = s[2], v3 = s[3];
    __half2 h[8];
    h[0] = __floats2half2_rn(v0.x, v0.y);   // k0,k1
    h[1] = __floats2half2_rn(v2.x, v2.y);   // k8,k9
    h[2] = __floats2half2_rn(v0.z, v0.w);   // k2,k3
    h[3] = __floats2half2_rn(v2.z, v2.w);   // k10,k11
    h[4] = __floats2half2_rn(v1.x, v1.y);   // k4,k5
    h[5] = __floats2half2_rn(v3.x, v3.y);   // k12,k13
    h[6] = __floats2half2_rn(v1.z, v1.w);   // k6,k7
    h[7] = __floats2half2_rn(v3.z, v3.w);   // k14,k15
    const uint32_t* hp = (const uint32_t*)h;
    uint4* d = (uint4*)(dst + (size_t)idx * 16);
    d[0] = make_uint4(hp[0], hp[1], hp[2], hp[3]);
    d[1] = make_uint4(hp[4], hp[5], hp[6], hp[7]);
}

// ======================= Kernel 1: w = exp(alpha . Wa + ba) =======================
__global__ void RA_w_kernel(const float* __restrict__ alpha, const float* __restrict__ Wa,
                            const float* __restrict__ ba) {
    __shared__ __align__(16) float sWa[HDIM];
    int tid = threadIdx.x;
    for (int i = tid; i < HDIM; i += blockDim.x) sWa[i] = Wa[i];
    __syncthreads();
    int wid = tid >> 5, lane = tid & 31;
    int row = blockIdx.x * 8 + wid;
    const float4* a4 = (const float4*)(alpha + (size_t)row * HDIM);
    const float4* w4 = (const float4*)sWa;
    float sum = 0.f;
#pragma unroll
    for (int i = 0; i < 4; i++) {
        float4 a = a4[lane + i * 32];
        float4 w = w4[lane + i * 32];
        sum += a.x * w.x + a.y * w.y + a.z * w.z + a.w * w.w;
    }
#pragma unroll
    for (int o = 16; o > 0; o >>= 1) sum += __shfl_xor_sync(0xffffffffu, sum, o);
    if (lane == 0) g_w[row] = expf(sum + ba[0]);
}

// ======================= Kernel 2: denInv = 1/(cumsum(w)+1e-10), per b =======================
__global__ void RA_den_kernel() {
    __shared__ float sw[SDIM];
    __shared__ float sx[32];
    int b = blockIdx.x, tid = threadIdx.x;
    for (int i = tid; i < SDIM; i += 256) sw[i] = g_w[b * SDIM + i];
    __syncthreads();
    if (tid < 32) {
        int lane = tid;
        int base = lane * 64;
        float s = 0.f;
        for (int i = 0; i < 64; i++) { s += sw[base + i]; sw[base + i] = s; }
        float tot = s;
#pragma unroll
        for (int o = 1; o < 32; o <<= 1) {
            float t = __shfl_up_sync(0xffffffffu, tot, o);
            if (lane >= o) tot += t;
        }
        sx[lane] = tot - s;
    }
    __syncthreads();
    float* di = g_denInv + b * SDIM;
    for (int i = tid; i < SDIM; i += 256)
        di[i] = 1.0f / (sw[i] + sx[i >> 6] + 1e-10f);
}

// ======================= Kernel 3: fp16 GEMM + epilogue + single-pass scan =======================
// 128x128 CTA tile, 256 threads, 8 warps of 32(M)x64(N), m16n8k16 fp16 MMA,
// NSTAGE=3 (CP_WAIT(1)), 2 CTAs/SM.
#define MT 128
#define NT 128
#define KB 32
#define KT (HDIM / KB)   // 16 k-tiles
#define NSTAGE 3
#define LDAH 48                       // 32 data halfs + 16 pad -> 96 B rows, conflict-free
#define A_ST_BYTES (MT * LDAH * 2)    // 12288
#define B_ST_BYTES (NT * LDAH * 2)    // 12288
#define ST_BYTES (A_ST_BYTES + B_ST_BYTES)  // 24576
#define EX_OFF (NSTAGE * ST_BYTES)          // 73728: float extras after pipe
#define GEMM_SMEM (EX_OFF + (NT + 4 * NT + NT) * 4)   // 76800 B -> 2 CTAs/SM

__device__ __forceinline__ void gemm_load_stage(char* smemc, int stg, int kt,
                                                int m0, int n0, int tid) {
    __half* sA = (__half*)(smemc + stg * ST_BYTES);
    __half* sB = (__half*)(smemc + stg * ST_BYTES + A_ST_BYTES);
    // A: 128 rows x 32 halfs = 512 16B-chunks; 256 thr -> 2 each
#pragma unroll
    for (int i = 0; i < 2; i++) {
        int id = tid + i * 256;
        int r = id >> 2, c = id & 3;
        cp16(sA + r * LDAH + c * 8, g_ahl + (size_t)(m0 + r) * HDIM + kt * KB + c * 8);
    }
#pragma unroll
    for (int i = 0; i < 2; i++) {
        int id = tid + i * 256;
        int r = id >> 2, c = id & 3;
        cp16(sB + r * LDAH + c * 8, g_bhl + (size_t)(n0 + r) * HDIM + kt * KB + c * 8);
    }
}

__global__ void __launch_bounds__(256, 2) RA_gemm_kernel(
    const float* __restrict__ bb,      // [EDIM]
    const float* __restrict__ embed,   // [ROWS, EDIM]
    float* __restrict__ out)           // [ROWS, EDIM]
{
    extern __shared__ char smemc[];
    int tid = threadIdx.x, wid = tid >> 5, lane = tid & 31;
    int g = lane >> 2, tg = lane & 3;
    int bx = blockIdx.x, by = blockIdx.y;
    int n0 = bx * NT, m0 = by * MT;
    int wm = wid & 3, wn = wid >> 2;   // 4 x 2 warp grid; warp tile 32(M) x 64(N)
    int t_local = by & 15;
    int mtile_base = by - t_local;

    float* sBB  = (float*)(smemc + EX_OFF);
    float* sCh  = sBB + NT;            // [4][NT]
    float* sPre = sCh + 4 * NT;
    if (tid < NT) sBB[tid] = bb[n0 + tid];

    gemm_load_stage(smemc, 0, 0, m0, n0, tid);
    CP_COMMIT();
    gemm_load_stage(smemc, 1, 1, m0, n0, tid);
    CP_COMMIT();

    float acc[2][8][4];
#pragma unroll
    for (int i = 0; i < 2; i++)
#pragma unroll
        for (int j = 0; j < 8; j++)
#pragma unroll
            for (int q = 0; q < 4; q++) acc[i][j][q] = 0.f;

    for (int kt = 0; kt < KT; kt++) {
        CP_WAIT(1);
        __syncthreads();
        if (kt + 2 < KT)
            gemm_load_stage(smemc, (kt + 2) % NSTAGE, kt + 2, m0, n0, tid);
        CP_COMMIT();   // always commit (possibly-empty group keeps ledger aligned)

        int buf = kt % NSTAGE;
        const char* stage = smemc + buf * ST_BYTES;
        const __half* sAh = (const __half*)stage + (wm * 32 + g) * LDAH + tg * 4;
        const __half* sBh = (const __half*)(stage + A_ST_BYTES) + (wn * 64 + g) * LDAH + tg * 4;
#pragma unroll
        for (int s = 0; s < 2; s++) {      // two k16 steps per kt
            uint32_t a[2][4];
#pragma unroll
            for (int i = 0; i < 2; i++) {
                uint2 lo = *(const uint2*)(sAh + (i * 16) * LDAH + s * 16);
                uint2 hi = *(const uint2*)(sAh + (i * 16 + 8) * LDAH + s * 16);
                a[i][0] = lo.x;   // (g,   k=2tg,2tg+1)
                a[i][2] = lo.y;   // (g,   k=2tg+8,2tg+9)
                a[i][1] = hi.x;   // (g+8, k=2tg,2tg+1)
                a[i][3] = hi.y;   // (g+8, k=2tg+8,2tg+9)
            }
#pragma unroll
            for (int j = 0; j < 8; j++) {
                uint2 lb = *(const uint2*)(sBh + (j * 8) * LDAH + s * 16);
#pragma unroll
                for (int i = 0; i < 2; i++) mma_f16(acc[i][j], a[i], lb.x, lb.y);
            }
        }
    }

    // ---- step 1: transform acc -> g values; per-column sums over this warp's 32 rows ----
    int m_base = m0 + wm * 32, n_base = n0 + wn * 64;
    float cs[8][2];
#pragma unroll
    for (int j = 0; j < 8; j++) { cs[j][0] = 0.f; cs[j][1] = 0.f; }

#pragma unroll
    for (int i = 0; i < 2; i++) {
#pragma unroll
        for (int r2 = 0; r2 < 2; r2++) {
            int row = m_base + i * 16 + r2 * 8 + g;
            float wr = g_w[row];
            const float* erow = embed + (size_t)row * EDIM;
#pragma unroll
            for (int j = 0; j < 8; j++) {
                int nc = n_base + j * 8 + tg * 2;
                float2 ee = *(const float2*)(erow + nc);
                float b0 = sBB[nc - n0], b1 = sBB[nc - n0 + 1];
                float vx = wr * tanh_fast(acc[i][j][r2 * 2 + 0] + b0) * ee.x;
                float vy = wr * tanh_fast(acc[i][j][r2 * 2 + 1] + b1) * ee.y;
                acc[i][j][r2 * 2 + 0] = vx;
                acc[i][j][r2 * 2 + 1] = vy;
                cs[j][0] += vx;
                cs[j][1] += vy;
            }
        }
    }
#pragma unroll
    for (int j = 0; j < 8; j++) {
#pragma unroll
        for (int q = 0; q < 2; q++) {
            float v = cs[j][q];
            v += __shfl_xor_sync(0xffffffffu, v, 4);
            v += __shfl_xor_sync(0xffffffffu, v, 8);
            v += __shfl_xor_sync(0xffffffffu, v, 16);
            cs[j][q] = v;
        }
    }
    // ---- step 2: stash 32-row block sums ----
    if (g == 0) {
        float* dst = sCh + wm * NT;
#pragma unroll
        for (int j = 0; j < 8; j++) {
            int c = wn * 64 + j * 8 + tg * 2;
            dst[c] = cs[j][0];
            dst[c + 1] = cs[j][1];
        }
    }
    __syncthreads();

    // ---- step 3: publish 128-row tile sum + release flag ----
    if (tid < NT) {
        float ts = sCh[tid] + sCh[NT + tid] + sCh[2 * NT + tid] + sCh[3 * NT + tid];
        g_tsum[(size_t)by * EDIM + n0 + tid] = ts;
    }
    __threadfence();
    __syncthreads();
    if (tid == 0)
        asm volatile("st.release.gpu.b32 [%0], %1;"
                     :: "l"(&g_flag[by * NBX + bx]), "r"(1u) : "memory");

    // ---- step 4: look-back ----
    if (tid < t_local) {
        const unsigned* f = &g_flag[(mtile_base + tid) * NBX + bx];
        unsigned v;
        unsigned ns = 64;
        for (;;) {
            asm volatile("ld.acquire.gpu.b32 %0, [%1];" : "=r"(v) : "l"(f) : "memory");
            if (v) break;
            __nanosleep(ns);
            if (ns < 1024) ns <<= 1;
        }
    }
    __syncthreads();
    if (tid < NT) {
        float p = 0.f;
        for (int q = 0; q < t_local; q++)
            p += g_tsum[(size_t)(mtile_base + q) * EDIM + n0 + tid];
        sPre[tid] = p;
    }
    __syncthreads();

    // ---- step 5: interleaved in-warp prefix + divide + store ----
    float dinv[4];
#pragma unroll
    for (int q = 0; q < 4; q++) dinv[q] = g_denInv[m_base + q * 8 + g];

#pragma unroll
    for (int j = 0; j < 8; j++) {
        int c = wn * 64 + j * 8 + tg * 2;
        float carryx = sPre[c], carryy = sPre[c + 1];
#pragma unroll
        for (int bblk = 0; bblk < 3; bblk++) {
            if (bblk < wm) {
                carryx += sCh[bblk * NT + c];
                carryy += sCh[bblk * NT + c + 1];
            }
        }
#pragma unroll
        for (int q = 0; q < 4; q++) {
            int i = q >> 1, r2 = q & 1;
            float sxv = acc[i][j][r2 * 2 + 0];
            float syv = acc[i][j][r2 * 2 + 1];
#pragma unroll
            for (int o = 4; o <= 16; o <<= 1) {
                float ux = __shfl_up_sync(0xffffffffu, sxv, o);
                float uy = __shfl_up_sync(0xffffffffu, syv, o);
                if (lane >= o) { sxv += ux; syv += uy; }
            }
            float totx = __shfl_sync(0xffffffffu, sxv, 28 + tg);
            float toty = __shfl_sync(0xffffffffu, syv, 28 + tg);
            int row = m_base + q * 8 + g;
            float d = dinv[q];
            float2 r;
            r.x = (carryx + sxv) * d;
            r.y = (carryy + syv) * d;
            *(float2*)(out + (size_t)row * EDIM + n_base + j * 8 + tg * 2) = r;
            carryx += totx;
            carryy += toty;
        }
    }
}

// ======================= Host launch =======================
extern "C" void kernel_launch(void* const* d_in, const int* in_sizes, int n_in,
                              void* d_out, int out_size) {
    const float* alpha   = (const float*)d_in[0];
    const float* beta_in = (const float*)d_in[1];
    const float* embed   = (const float*)d_in[2];
    const float* Wb      = (const float*)d_in[3];
    const float* bb      = (const float*)d_in[4];
    const float* Wa      = (const float*)d_in[5];
    const float* ba      = (const float*)d_in[6];
    float* out = (float*)d_out;

    __half* d_ahl; cudaGetSymbolAddress((void**)&d_ahl, g_ahl);
    __half* d_bhl; cudaGetSymbolAddress((void**)&d_bhl, g_bhl);

    RA_reset_kernel<<<MTILES * NBX / 256, 256>>>();
    RA_w_kernel<<<ROWS / 8, 256>>>(alpha, Wa, ba);
    RA_den_kernel<<<BDIM, 256>>>();
    RA_tohalf_kernel<<<(ROWS * (HDIM / 16)) / 256, 256>>>(beta_in, d_ahl, ROWS * (HDIM / 16));
    RA_tohalf_kernel<<<(EDIM * (HDIM / 16)) / 256, 256>>>(Wb, d_bhl, EDIM * (HDIM / 16));
    cudaFuncSetAttribute(RA_gemm_kernel, cudaFuncAttributeMaxDynamicSharedMemorySize, GEMM_SMEM);
    RA_gemm_kernel<<<dim3(NBX, ROWS / MT), 256, GEMM_SMEM>>>(bb, embed, out);
    (void)in_sizes; (void)n_in; (void)out_size;
}